// round 8
// baseline (speedup 1.0000x reference)
#include <cuda_runtime.h>

#define TSTEPS   512
#define NTHREADS 1024

// Padded strides (floats)
#define WSTRIDE  68     // weight row [Wih|Whh] = 64 + 4 pad
#define ISTRIDE  68     // input row per batch: 64 k + 4 pad
#define GSTRIDE  34     // gs row per gate: 32 b + 2 pad

// Dynamic smem layout (float offsets, 16B aligned)
#define OFF_W0    0                          // 128*68
#define OFF_W1    (OFF_W0 + 128*WSTRIDE)
#define OFF_GS    (OFF_W1 + 128*WSTRIDE)     // 128*34
#define OFF_IN0   (OFF_GS + 128*GSTRIDE)     // 32*68 layer0 input [x | h0], [b][k]
#define OFF_INB   (OFF_IN0 + 32*ISTRIDE)     // layer1 input [h0 | h1]
#define OFF_B0    (OFF_INB + 32*ISTRIDE)     // 128
#define OFF_B1    (OFF_B0 + 128)             // 128
#define OFF_W1S   (OFF_B1 + 128)             // 32
#define OFF_B1S   (OFF_W1S + 32)             // 32
#define OFF_W2S   (OFF_B1S + 32)             // 64
#define SMEM_FLOATS (OFF_W2S + 64)
#define SMEM_BYTES  (SMEM_FLOATS * 4)        // 105984

typedef unsigned long long ull;

__device__ __forceinline__ void upk2(ull v, float& lo, float& hi) {
    asm("mov.b64 {%0,%1}, %2;" : "=f"(lo), "=f"(hi) : "l"(v));
}
__device__ __forceinline__ void ffma2(ull& d, ull a, ull b) {
    asm("fma.rn.f32x2 %0, %1, %2, %0;" : "+l"(d) : "l"(a), "l"(b));
}
__device__ __forceinline__ float sigm(float v) {
    float e = __expf(-v);
    return __fdividef(1.0f, 1.0f + e);
}
__device__ __forceinline__ float tanh_(float v) {
    float e = __expf(-2.0f * v);
    return __fdividef(2.0f, 1.0f + e) - 1.0f;
}

// Thread computes gate rows {gbase, gbase+64} x batches {2bp, 2bp+1}.
// Per warp: 8 distinct gate rows (lg) -> 128B unique weights per LDS.128 wavefront;
// 4 distinct batch rows (lb) -> 64B unique inputs per wavefront.
__device__ __forceinline__ void gate_phase(const float* __restrict__ Ws,
                                           const float* __restrict__ inX,
                                           float* __restrict__ gs,
                                           int gbase, int bp,
                                           float bzA, float bzB) {
    ull aE0 = 0, aO0 = 0, aE1 = 0, aO1 = 0;   // row gbase,   batch 0/1
    ull bE0 = 0, bO0 = 0, bE1 = 0, bO1 = 0;   // row gbase+64, batch 0/1
    const float* wA  = Ws + gbase * WSTRIDE;
    const float* wB  = Ws + (gbase + 64) * WSTRIDE;
    const float* ib0 = inX + (2 * bp) * ISTRIDE;
    const float* ib1 = ib0 + ISTRIDE;
#pragma unroll
    for (int kq = 0; kq < 16; kq++) {
        ulonglong2 i0 = *(const ulonglong2*)(ib0 + 4 * kq);
        ulonglong2 i1 = *(const ulonglong2*)(ib1 + 4 * kq);
        ulonglong2 wa = *(const ulonglong2*)(wA + 4 * kq);
        ulonglong2 wb = *(const ulonglong2*)(wB + 4 * kq);
        ffma2(aE0, wa.x, i0.x);  ffma2(aO0, wa.y, i0.y);
        ffma2(aE1, wa.x, i1.x);  ffma2(aO1, wa.y, i1.y);
        ffma2(bE0, wb.x, i0.x);  ffma2(bO0, wb.y, i0.y);
        ffma2(bE1, wb.x, i1.x);  ffma2(bO1, wb.y, i1.y);
    }
    float l0, h0, l1, h1;
    upk2(aE0, l0, h0); upk2(aO0, l1, h1);
    float gA0 = (l0 + h0) + (l1 + h1) + bzA;
    upk2(aE1, l0, h0); upk2(aO1, l1, h1);
    float gA1 = (l0 + h0) + (l1 + h1) + bzA;
    upk2(bE0, l0, h0); upk2(bO0, l1, h1);
    float gB0 = (l0 + h0) + (l1 + h1) + bzB;
    upk2(bE1, l0, h0); upk2(bO1, l1, h1);
    float gB1 = (l0 + h0) + (l1 + h1) + bzB;
    *(float2*)&gs[gbase * GSTRIDE + 2 * bp]        = make_float2(gA0, gA1);
    *(float2*)&gs[(gbase + 64) * GSTRIDE + 2 * bp] = make_float2(gB0, gB1);
}

// Update: thread (uj, ub) owns hidden unit uj at batch ub.
__device__ __forceinline__ float update1(const float* __restrict__ gs,
                                         int uj, int ub, float& c) {
    float iv = sigm(gs[(uj)      * GSTRIDE + ub]);
    float fv = sigm(gs[(32 + uj) * GSTRIDE + ub]);
    float gv = tanh_(gs[(64 + uj) * GSTRIDE + ub]);
    float ov = sigm(gs[(96 + uj) * GSTRIDE + ub]);
    c = fmaf(fv, c, iv * gv);
    return ov * tanh_(c);
}

__global__ void __launch_bounds__(NTHREADS, 1)
lstm_fused_kernel(const float* __restrict__ tensor,
                  const float* __restrict__ w1,   const float* __restrict__ b1,
                  const float* __restrict__ Wih0, const float* __restrict__ Whh0,
                  const float* __restrict__ bih0, const float* __restrict__ bhh0,
                  const float* __restrict__ Wih1, const float* __restrict__ Whh1,
                  const float* __restrict__ bih1, const float* __restrict__ bhh1,
                  const float* __restrict__ w2,   const float* __restrict__ b2,
                  float* __restrict__ out) {
    extern __shared__ float smem[];
    float* W0s   = smem + OFF_W0;
    float* W1s   = smem + OFF_W1;
    float* gs    = smem + OFF_GS;
    float* in0   = smem + OFF_IN0;
    float* inB   = smem + OFF_INB;
    float* bias0 = smem + OFF_B0;
    float* bias1 = smem + OFF_B1;
    float* w1s   = smem + OFF_W1S;
    float* b1s   = smem + OFF_B1S;
    float* w2s   = smem + OFF_W2S;

    const int tid = threadIdx.x;
    const int l   = tid & 31;
    const int wrp = tid >> 5;
    // Gate-phase mapping
    const int lg = l & 7;
    const int lb = l >> 3;
    const int gw = wrp & 7;
    const int bw = wrp >> 3;
    const int gbase = gw * 8 + lg;    // 0..63 -> rows gbase, gbase+64
    const int bp    = bw * 4 + lb;    // 0..15 -> batches 2bp, 2bp+1
    // Update-phase mapping
    const int uj = tid & 31;          // hidden unit
    const int ub = tid >> 5;          // batch

    // ---- Preload weights / biases into SMEM ----
    for (int idx = tid; idx < 128 * 32; idx += NTHREADS) {
        int g = idx >> 5, k = idx & 31;
        W0s[g * WSTRIDE + k]      = Wih0[idx];
        W0s[g * WSTRIDE + 32 + k] = Whh0[idx];
        W1s[g * WSTRIDE + k]      = Wih1[idx];
        W1s[g * WSTRIDE + 32 + k] = Whh1[idx];
    }
    if (tid < 128) {
        bias0[tid] = bih0[tid] + bhh0[tid];
        bias1[tid] = bih1[tid] + bhh1[tid];
    }
    if (tid < 32) { w1s[tid] = w1[tid]; b1s[tid] = b1[tid]; }
    if (tid < 64) { w2s[tid] = w2[tid]; }
    __syncthreads();

    // hoisted per-thread constants
    const float bz00 = bias0[gbase], bz01 = bias0[gbase + 64];
    const float bz10 = bias1[gbase], bz11 = bias1[gbase + 64];
    const float w1j  = w1s[uj], b1j = b1s[uj];
    const float* __restrict__ seq = tensor + (long)(blockIdx.x * 32 + ub) * TSTEPS;

    // ---- Init staging: x(t=0); h0 = h1 = 0 ----
    {
        float x0 = fmaxf(fmaf(seq[0], w1j, b1j), 0.f);
        in0[ub * ISTRIDE + uj]      = x0;
        in0[ub * ISTRIDE + 32 + uj] = 0.f;
        inB[ub * ISTRIDE + uj]      = 0.f;
        inB[ub * ISTRIDE + 32 + uj] = 0.f;
    }
    float c0 = 0.f, c1 = 0.f;
    __syncthreads();

    for (int t = 0; t < TSTEPS; t++) {
        // ---- Layer 0 gates ----
        gate_phase(W0s, in0, gs, gbase, bp, bz00, bz01);
        __syncthreads();                                   // S1: gates0 ready

        // ---- Layer 0 update + next-step x ----
        {
            float h0 = update1(gs, uj, ub, c0);
            in0[ub * ISTRIDE + 32 + uj] = h0;              // h0 -> next-step L0 input
            inB[ub * ISTRIDE + uj]      = h0;              // h0 -> L1 input
            float s = (t + 1 < TSTEPS) ? seq[t + 1] : 0.f;
            in0[ub * ISTRIDE + uj] = fmaxf(fmaf(s, w1j, b1j), 0.f);
        }
        __syncthreads();                                   // S2: inB / in0 ready

        // ---- Layer 1 gates ----
        gate_phase(W1s, inB, gs, gbase, bp, bz10, bz11);
        __syncthreads();                                   // S3: gates1 ready

        // ---- Layer 1 update ----
        {
            float h1 = update1(gs, uj, ub, c1);
            inB[ub * ISTRIDE + 32 + uj] = h1;              // h1 -> next-step L1 input
        }
        __syncthreads();                                   // S4
    }

    // ---- Head: out[b] = [h0_final ; h1_final] . w2 + b2 ----
    if (tid < 32) {
        const float* h0p = in0 + tid * ISTRIDE + 32;
        const float* h1p = inB + tid * ISTRIDE + 32;
        float acc = 0.f;
#pragma unroll
        for (int k = 0; k < 32; k++) acc = fmaf(w2s[k], h0p[k], acc);
#pragma unroll
        for (int k = 0; k < 32; k++) acc = fmaf(w2s[32 + k], h1p[k], acc);
        out[blockIdx.x * 32 + tid] = acc + b2[0];
    }
}

extern "C" void kernel_launch(void* const* d_in, const int* in_sizes, int n_in,
                              void* d_out, int out_size) {
    const float* tensor = (const float*)d_in[0];
    const float* w1     = (const float*)d_in[1];
    const float* b1     = (const float*)d_in[2];
    const float* Wih0   = (const float*)d_in[3];
    const float* Whh0   = (const float*)d_in[4];
    const float* bih0   = (const float*)d_in[5];
    const float* bhh0   = (const float*)d_in[6];
    const float* Wih1   = (const float*)d_in[7];
    const float* Whh1   = (const float*)d_in[8];
    const float* bih1   = (const float*)d_in[9];
    const float* bhh1   = (const float*)d_in[10];
    const float* w2     = (const float*)d_in[11];
    const float* b2     = (const float*)d_in[12];
    float* out = (float*)d_out;

    int Btot = in_sizes[0] / TSTEPS;   // 4096
    int grid = (Btot + 31) / 32;       // 128 CTAs

    cudaFuncSetAttribute(lstm_fused_kernel,
                         cudaFuncAttributeMaxDynamicSharedMemorySize, SMEM_BYTES);
    lstm_fused_kernel<<<grid, NTHREADS, SMEM_BYTES>>>(
        tensor, w1, b1, Wih0, Whh0, bih0, bhh0,
        Wih1, Whh1, bih1, bhh1, w2, b2, out);
}